// round 15
// baseline (speedup 1.0000x reference)
#include <cuda_runtime.h>
#include <cuda_fp16.h>
#include <math.h>
#include <stdint.h>

static constexpr int B_ = 4, S_ = 1024, DM_ = 1024, H_ = 16, DK_ = 64, DV_ = 64;
static constexpr int NX_ = B_*S_*DM_;     // 4M elements (q/k/v)
static constexpr int NWO_ = DM_*H_*DV_;   // 1M elements (Wo)
static constexpr float LOG2E = 1.44269504088896f;
static constexpr int KW = 40;             // smem row stride (words); LDS.64 conflict-free

// Scratch (device globals). fp16x2 words, PERMUTED within each 8-word group:
// positions [w0,w4,w1,w5,w2,w6,w3,w7] so mma fragment pairs (w,w+4) are adjacent.
__device__ uint32_t g_qH[NX_/2], g_kH[NX_/2], g_vH[NX_/2];     // [m][512w]
__device__ uint32_t g_WqH[H_*DK_*DM_/2], g_WkH[H_*DK_*DM_/2], g_WvH[H_*DK_*DM_/2]; // [h][dk][512w]
__device__ uint32_t g_WoH[NWO_/2];                             // [d][512w]
__device__ uint32_t g_QH[B_*H_*S_*DK_/2];  // [b,h,s,32w] fp16, scaled log2e/8
__device__ uint32_t g_KH[B_*H_*S_*DK_/2];  // [b,h,s,32w]
__device__ uint32_t g_VH[B_*H_*DV_*S_/2];  // V^T: [b,h,dv][512w] pairs along seq
__device__ uint32_t g_XH[B_*S_*H_*DV_/2];  // [b,s,512w]

__device__ __forceinline__ uint32_t f2h2(float a, float b) {
    __half2 h = __floats2half2_rn(a, b);
    return *(uint32_t*)&h;
}
__device__ __forceinline__ float ex2(float x) {
    float r; asm("ex2.approx.f32 %0, %1;" : "=f"(r) : "f"(x)); return r;
}
__device__ __forceinline__ int permw(int w) {          // in-group permutation
    int t = w & 7;
    return (w & ~7) | ((t < 4) ? 2 * t : 2 * (t - 4) + 1);
}

// fp16 m16n8k16, fp32 accumulate
__device__ __forceinline__ void mma16(float* c, const uint32_t* a, const uint32_t* b) {
    asm volatile(
        "mma.sync.aligned.m16n8k16.row.col.f32.f16.f16.f32 "
        "{%0,%1,%2,%3}, {%4,%5,%6,%7}, {%8,%9}, {%0,%1,%2,%3};"
        : "+f"(c[0]), "+f"(c[1]), "+f"(c[2]), "+f"(c[3])
        : "r"(a[0]), "r"(a[1]), "r"(a[2]), "r"(a[3]), "r"(b[0]), "r"(b[1]));
}

__device__ __forceinline__ void cpa16(void* smem_ptr, const void* gptr) {
    uint32_t s = (uint32_t)__cvta_generic_to_shared(smem_ptr);
    asm volatile("cp.async.cg.shared.global [%0], [%1], 16;" :: "r"(s), "l"(gptr));
}
__device__ __forceinline__ void cpa_commit() { asm volatile("cp.async.commit_group;"); }
__device__ __forceinline__ void cpa_wait0()  { asm volatile("cp.async.wait_group 0;"); }
__device__ __forceinline__ void cpa_wait1()  { asm volatile("cp.async.wait_group 1;"); }

// ---------------------------------------------------------------------------
// Kernel 0a: convert+pack q/k/v/Wo -> permuted fp16x2 (16 elems / thread).
// ---------------------------------------------------------------------------
__global__ __launch_bounds__(256) void cvt_pack(
    const float* __restrict__ q, const float* __restrict__ k, const float* __restrict__ v,
    const float* __restrict__ Wo)
{
    const float* src; uint32_t* dst; int n;
    switch (blockIdx.y) {
        case 0: src = q;  dst = g_qH;  n = NX_;  break;
        case 1: src = k;  dst = g_kH;  n = NX_;  break;
        case 2: src = v;  dst = g_vH;  n = NX_;  break;
        default: src = Wo; dst = g_WoH; n = NWO_; break;
    }
    int i = (blockIdx.x * 256 + threadIdx.x) * 16;
    if (i < n) {
        float4 a = *(const float4*)&src[i];
        float4 b = *(const float4*)&src[i + 4];
        float4 c = *(const float4*)&src[i + 8];
        float4 d = *(const float4*)&src[i + 12];
        uint32_t w0 = f2h2(a.x, a.y), w1 = f2h2(a.z, a.w);
        uint32_t w2 = f2h2(b.x, b.y), w3 = f2h2(b.z, b.w);
        uint32_t w4 = f2h2(c.x, c.y), w5 = f2h2(c.z, c.w);
        uint32_t w6 = f2h2(d.x, d.y), w7 = f2h2(d.z, d.w);
        *(uint4*)&dst[i / 2]     = make_uint4(w0, w4, w1, w5);
        *(uint4*)&dst[i / 2 + 4] = make_uint4(w2, w6, w3, w7);
    }
}

// ---------------------------------------------------------------------------
// Kernel 0b: transpose+pack Wq/Wk/Wv -> [h][dk][dm/2 words], permuted.
// ---------------------------------------------------------------------------
__global__ __launch_bounds__(256) void cvt_wT(
    const float* __restrict__ Wq, const float* __restrict__ Wk, const float* __restrict__ Wv)
{
    const float* src; uint32_t* dst;
    if (blockIdx.z == 0)      { src = Wq; dst = g_WqH; }
    else if (blockIdx.z == 1) { src = Wk; dst = g_WkH; }
    else                      { src = Wv; dst = g_WvH; }

    const int h = blockIdx.y, d0 = blockIdx.x * 32;
    __shared__ float t[2][32][33];
    const float* Wh = src + (size_t)h * DM_ * DK_;
    for (int u = threadIdx.x; u < 2048; u += 256) {
        int i = u >> 6, nk = u & 63;
        t[nk >> 5][i][nk & 31] = Wh[(size_t)(d0 + i) * DK_ + nk];
    }
    __syncthreads();
    uint32_t* Dh = dst + (size_t)h * DK_ * (DM_ / 2);
    for (int u = threadIdx.x; u < 1024; u += 256) {
        int nk = u >> 4, i = u & 15;
        Dh[(size_t)nk * (DM_ / 2) + d0 / 2 + permw(i)] =
            f2h2(t[nk >> 5][2 * i][nk & 31], t[nk >> 5][2 * i + 1][nk & 31]);
    }
}

// ---------------------------------------------------------------------------
// Kernel 1: fused QKV projections. Block 128M x 128N(=2 heads), 8 warps
// (4m x 2n), warp 32x64, K-chunk 64 (32w), 2-stage cp.async, LDS.64 frags.
// ---------------------------------------------------------------------------
__global__ __launch_bounds__(256, 2) void qkv_proj_mma()
{
    extern __shared__ uint32_t smq[];
    uint32_t (*As)[128][KW] = (uint32_t(*)[128][KW])smq;                // 2 bufs
    uint32_t (*Bs)[128][KW] = (uint32_t(*)[128][KW])(smq + 2*128*KW);   // 2 bufs [n][kw]

    const uint32_t* x; const uint32_t* W; const int zsel = blockIdx.z;
    if (zsel == 0)      { x = g_qH; W = g_WqH; }
    else if (zsel == 1) { x = g_kH; W = g_WkH; }
    else                { x = g_vH; W = g_WvH; }

    const int m0 = blockIdx.x * 128;
    const int hp = blockIdx.y;

    const int tid = threadIdx.x, lane = tid & 31, warp = tid >> 5;
    const int wm = warp & 3, wn = warp >> 2;
    const int g = lane >> 2, tig = lane & 3;

    float acc[2][8][4];
    #pragma unroll
    for (int mt = 0; mt < 2; mt++)
        #pragma unroll
        for (int nt = 0; nt < 8; nt++)
            #pragma unroll
            for (int i = 0; i < 4; i++) acc[mt][nt][i] = 0.f;

    auto issue = [&](int k0w, int buf) {
        #pragma unroll
        for (int t = 0; t < 4; t++) {
            int idx = tid + t * 256, r = idx >> 3, c = (idx & 7) * 4;
            cpa16(&As[buf][r][c], &x[(size_t)(m0 + r) * (DM_/2) + k0w + c]);
        }
        #pragma unroll
        for (int t = 0; t < 4; t++) {
            int idx = tid + t * 256, r = idx >> 3, c = (idx & 7) * 4;
            int h = 2 * hp + (r >> 6), nk = r & 63;
            cpa16(&Bs[buf][r][c], &W[((size_t)h * DK_ + nk) * (DM_/2) + k0w + c]);
        }
        cpa_commit();
    };

    issue(0, 0);
    const int NCH = DM_ / 64;
    for (int it = 0; it < NCH; it++) {
        const int buf = it & 1;
        cpa_wait0();
        __syncthreads();
        if (it + 1 < NCH) issue((it + 1) * 32, buf ^ 1);

        #pragma unroll
        for (int ks = 0; ks < 4; ks++) {
            uint32_t af[2][4];
            #pragma unroll
            for (int mt = 0; mt < 2; mt++) {
                int rr = wm * 32 + mt * 16 + g;
                uint2 ua = *(const uint2*)&As[buf][rr][ks*8 + 2*tig];
                uint2 ub = *(const uint2*)&As[buf][rr + 8][ks*8 + 2*tig];
                af[mt][0] = ua.x; af[mt][1] = ub.x; af[mt][2] = ua.y; af[mt][3] = ub.y;
            }
            #pragma unroll
            for (int nt = 0; nt < 8; nt++) {
                int n = wn * 64 + nt * 8 + g;
                uint2 vb = *(const uint2*)&Bs[buf][n][ks*8 + 2*tig];
                uint32_t bf[2] = {vb.x, vb.y};
                mma16(acc[0][nt], af[0], bf);
                mma16(acc[1][nt], af[1], bf);
            }
        }
    }

    if (zsel == 2) {
        // ---- V: smem transpose, emit V^T [b,h,dv][s words] (permuted) ----
        __syncthreads();
        __half (*smemN)[136] = (__half(*)[136])smq;
        #pragma unroll
        for (int mt = 0; mt < 2; mt++)
            #pragma unroll
            for (int hf = 0; hf < 2; hf++) {
                int lm = wm * 32 + mt * 16 + g + hf * 8;
                #pragma unroll
                for (int nt = 0; nt < 8; nt++) {
                    int c0 = wn * 64 + nt * 8 + 2 * tig;
                    float v0 = hf ? acc[mt][nt][2] : acc[mt][nt][0];
                    float v1 = hf ? acc[mt][nt][3] : acc[mt][nt][1];
                    *(__half2*)&smemN[lm][c0] = __floats2half2_rn(v0, v1);
                }
            }
        __syncthreads();
        const int b = m0 >> 10, s0 = m0 & 1023;
        #pragma unroll
        for (int t = 0; t < 32; t++) {
            int u = tid + t * 256;
            int r = u >> 6, w = u & 63;
            int h = 2 * hp + (r >> 6), dv = r & 63;
            __half2 hh;
            hh.x = smemN[2 * w][r];
            hh.y = smemN[2 * w + 1][r];
            g_VH[(((size_t)b * H_ + h) * DV_ + dv) * (S_/2) + s0 / 2 + permw(w)] = *(uint32_t*)&hh;
        }
    } else {
        const int h = 2 * hp + wn;
        const float sc = (zsel == 0) ? 0.125f * LOG2E : 1.f;
        uint32_t* outb = (zsel == 0) ? g_QH : g_KH;
        #pragma unroll
        for (int mt = 0; mt < 2; mt++) {
            #pragma unroll
            for (int hf = 0; hf < 2; hf++) {
                int m = m0 + wm * 32 + mt * 16 + g + hf * 8;
                int b = m >> 10, s = m & 1023;
                uint32_t* op = outb + (((size_t)b * H_ + h) * S_ + s) * (DK_/2);
                #pragma unroll
                for (int nt = 0; nt < 8; nt++) {
                    float v0 = hf ? acc[mt][nt][2] : acc[mt][nt][0];
                    float v1 = hf ? acc[mt][nt][3] : acc[mt][nt][1];
                    op[(nt >> 1) * 8 + 2 * tig + (nt & 1)] = f2h2(v0 * sc, v1 * sc);
                }
            }
        }
    }
}

// ---------------------------------------------------------------------------
// Kernel 2: causal flash attention, fp16 mma16, maxless log2-softmax.
// 8 warps = 4 row-groups (32 rows) x 2 key/dv-halves (32 each): K/V fragment
// traffic halves. P-store -> P.V synced by named pair barrier (wm+1, 64 thr).
// Partial row sums combined via Lp[128][2]. Grid (4,64); qt = 7-bx then bx.
// ---------------------------------------------------------------------------
__global__ __launch_bounds__(256, 2) void attn_mma()
{
    extern __shared__ uint32_t sm[];
    uint32_t (*Ks)[64][KW] = (uint32_t(*)[64][KW])sm;                // 2 bufs [key][kw]
    uint32_t (*Vs)[64][KW] = (uint32_t(*)[64][KW])(sm + 2*64*KW);    // 2 bufs [dv][keyw]
    uint32_t (*Qs)[KW]     = (uint32_t(*)[KW])(sm + 4*64*KW);        // 128 x KW
    uint32_t (*Ps)[KW]     = (uint32_t(*)[KW])(sm + 4*64*KW + 128*KW); // 128 x KW
    __shared__ float Lp[128][2];

    const int bh = blockIdx.y;
    const int b = bh >> 4, h = bh & 15;
    const int tid = threadIdx.x, lane = tid & 31, warp = tid >> 5;
    const int wm = warp & 3, wn = warp >> 2;
    const int g = lane >> 2, tig = lane & 3;

    const uint32_t* Kg = g_KH + (size_t)bh * S_ * (DK_/2);
    const uint32_t* Vg = g_VH + (size_t)bh * DV_ * (S_/2);

    for (int ph = 0; ph < 2; ph++) {
        const int qt = ph == 0 ? 7 - (int)blockIdx.x : (int)blockIdx.x;
        const uint32_t* Qg = g_QH + (size_t)bh * S_ * (DK_/2) + (size_t)qt * 128 * (DK_/2);

        __syncthreads();     // all warps done with prior phase smem
        #pragma unroll
        for (int t = 0; t < 4; t++) {
            int idx = tid + t * 256, r = idx >> 3, c = (idx & 7) * 4;
            cpa16(&Qs[r][c], &Qg[r * (DK_/2) + c]);
        }
        cpa_commit();

        auto issueKV = [&](int j, int buf) {
            const uint32_t* Kt = Kg + (size_t)j * 64 * (DK_/2);
            #pragma unroll
            for (int t = 0; t < 2; t++) {
                int idx = tid + t * 256, r = idx >> 3, c = (idx & 7) * 4;
                cpa16(&Ks[buf][r][c], &Kt[r * (DK_/2) + c]);
            }
            #pragma unroll
            for (int t = 0; t < 2; t++) {
                int idx = tid + t * 256, r = idx >> 3, c = (idx & 7) * 4;
                cpa16(&Vs[buf][r][c], &Vg[r * (S_/2) + j * 32 + c]);
            }
            cpa_commit();
        };

        float O[2][4][4];
        #pragma unroll
        for (int mt = 0; mt < 2; mt++)
            #pragma unroll
            for (int nt = 0; nt < 4; nt++)
                #pragma unroll
                for (int i = 0; i < 4; i++) O[mt][nt][i] = 0.f;
        float lsp[2][2] = {{0.f, 0.f}, {0.f, 0.f}};

        const int base = qt * 128 + wm * 32;
        const int jmax = 2 * qt + 1;

        issueKV(0, 0);   // group: {Q, KV0}

        for (int j = 0; j <= jmax; j++) {
            const int buf = j & 1;
            __syncthreads();             // prior tile's compute done
            if (j < jmax) { issueKV(j + 1, buf ^ 1); cpa_wait1(); }
            else          { cpa_wait0(); }
            __syncthreads();             // tile j (and Q on j=0) visible

            if (j * 64 > base + 31) continue;

            // ---- S = Q K^T (log2 domain): 32 rows x 32 keys per warp ----
            float Sf[2][4][4];
            #pragma unroll
            for (int mt = 0; mt < 2; mt++)
                #pragma unroll
                for (int nt = 0; nt < 4; nt++)
                    #pragma unroll
                    for (int i = 0; i < 4; i++) Sf[mt][nt][i] = 0.f;

            #pragma unroll
            for (int ks = 0; ks < 4; ks++) {
                uint32_t af[2][4];
                #pragma unroll
                for (int mt = 0; mt < 2; mt++) {
                    int rr = wm * 32 + mt * 16 + g;
                    uint2 ua = *(const uint2*)&Qs[rr][ks*8 + 2*tig];
                    uint2 ub = *(const uint2*)&Qs[rr + 8][ks*8 + 2*tig];
                    af[mt][0] = ua.x; af[mt][1] = ub.x; af[mt][2] = ua.y; af[mt][3] = ub.y;
                }
                #pragma unroll
                for (int nt = 0; nt < 4; nt++) {
                    uint2 vb = *(const uint2*)&Ks[buf][wn*32 + nt*8 + g][ks*8 + 2*tig];
                    uint32_t bf[2] = {vb.x, vb.y};
                    mma16(Sf[0][nt], af[0], bf);
                    mma16(Sf[1][nt], af[1], bf);
                }
            }

            // ---- causal mask ----
            if ((j + 1) * 64 > base) {
                #pragma unroll
                for (int mt = 0; mt < 2; mt++) {
                    int r0 = base + mt * 16 + g - j * 64, r1 = r0 + 8;
                    #pragma unroll
                    for (int nt = 0; nt < 4; nt++) {
                        int c0 = wn * 32 + nt * 8 + 2 * tig, c1 = c0 + 1;
                        if (c0 > r0) Sf[mt][nt][0] = -1e30f;
                        if (c1 > r0) Sf[mt][nt][1] = -1e30f;
                        if (c0 > r1) Sf[mt][nt][2] = -1e30f;
                        if (c1 > r1) Sf[mt][nt][3] = -1e30f;
                    }
                }
            }

            // ---- maxless softmax: p = 2^s ----
            #pragma unroll
            for (int mt = 0; mt < 2; mt++) {
                #pragma unroll
                for (int hp = 0; hp < 2; hp++) {
                    const int rr = wm * 32 + mt * 16 + g + 8 * hp;
                    float ls = 0.f;
                    #pragma unroll
                    for (int ntp = 0; ntp < 2; ntp++) {
                        const int nt0 = 2 * ntp, nt1 = nt0 + 1;
                        float p00 = ex2(Sf[mt][nt0][2*hp]);
                        float p01 = ex2(Sf[mt][nt0][2*hp + 1]);
                        float p10 = ex2(Sf[mt][nt1][2*hp]);
                        float p11 = ex2(Sf[mt][nt1][2*hp + 1]);
                        ls += (p00 + p01) + (p10 + p11);
                        *(uint2*)&Ps[rr][wn*16 + ntp*8 + 2*tig] =
                            make_uint2(f2h2(p00, p01), f2h2(p10, p11));
                    }
                    lsp[mt][hp] += ls;
                }
            }
            asm volatile("bar.sync %0, %1;" :: "r"(wm + 1), "r"(64) : "memory");

            // ---- O += P V (full 64 keys, dv half per warp) ----
            #pragma unroll
            for (int kt = 0; kt < 4; kt++) {
                uint32_t af[2][4];
                #pragma unroll
                for (int mt = 0; mt < 2; mt++) {
                    int rr = wm * 32 + mt * 16 + g;
                    uint2 ua = *(const uint2*)&Ps[rr][kt*8 + 2*tig];
                    uint2 ub = *(const uint2*)&Ps[rr + 8][kt*8 + 2*tig];
                    af[mt][0] = ua.x; af[mt][1] = ub.x; af[mt][2] = ua.y; af[mt][3] = ub.y;
                }
                #pragma unroll
                for (int nt = 0; nt < 4; nt++) {
                    uint2 vb = *(const uint2*)&Vs[buf][wn*32 + nt*8 + g][kt*8 + 2*tig];
                    uint32_t bf[2] = {vb.x, vb.y};
                    mma16(O[0][nt], af[0], bf);
                    mma16(O[1][nt], af[1], bf);
                }
            }
        }

        // ---- combine partial row sums across the wn pair ----
        #pragma unroll
        for (int mt = 0; mt < 2; mt++)
            #pragma unroll
            for (int hp = 0; hp < 2; hp++) {
                float ls = lsp[mt][hp];
                ls += __shfl_xor_sync(0xffffffffu, ls, 1);
                ls += __shfl_xor_sync(0xffffffffu, ls, 2);
                if (tig == 0) Lp[wm*32 + mt*16 + g + 8*hp][wn] = ls;
            }
        __syncthreads();

        // ---- epilogue: normalize and pack X (permuted fp16x2) ----
        #pragma unroll
        for (int mt = 0; mt < 2; mt++) {
            #pragma unroll
            for (int hp = 0; hp < 2; hp++) {
                const int rl_row = wm*32 + mt*16 + g + 8*hp;
                const float rl = 1.f / (Lp[rl_row][0] + Lp[rl_row][1]);
                const int row = qt * 128 + rl_row;
                uint32_t* xp = g_XH + ((size_t)b * S_ + row) * (H_ * DV_ / 2) + h * (DV_/2);
                #pragma unroll
                for (int nt = 0; nt < 4; nt++) {
                    int ntg = wn * 4 + nt;
                    xp[(ntg >> 1) * 8 + 2 * tig + (ntg & 1)] =
                        f2h2(O[mt][nt][2*hp] * rl, O[mt][nt][2*hp + 1] * rl);
                }
            }
        }
    }
}

// ---------------------------------------------------------------------------
// Kernel 3: output projection. Block 128x128, 8 warps (4m x 2n), warp 32x64,
// K-chunk 64, 2-stage ring, LDS.64 fragments.
// ---------------------------------------------------------------------------
__global__ __launch_bounds__(256, 2) void out_proj_mma(float* __restrict__ y)
{
    extern __shared__ uint32_t smo[];
    uint32_t (*As)[128][KW]  = (uint32_t(*)[128][KW])smo;
    uint32_t (*Bsn)[128][KW] = (uint32_t(*)[128][KW])(smo + 2*128*KW);

    const int m0 = blockIdx.x * 128;
    const int n0 = blockIdx.y * 128;

    const int tid = threadIdx.x, lane = tid & 31, warp = tid >> 5;
    const int wm = warp & 3, wn = warp >> 2;
    const int g = lane >> 2, tig = lane & 3;

    float acc[2][8][4];
    #pragma unroll
    for (int mt = 0; mt < 2; mt++)
        #pragma unroll
        for (int nt = 0; nt < 8; nt++)
            #pragma unroll
            for (int i = 0; i < 4; i++) acc[mt][nt][i] = 0.f;

    auto issue = [&](int k0w, int buf) {
        #pragma unroll
        for (int t = 0; t < 4; t++) {
            int idx = tid + t * 256, r = idx >> 3, c = (idx & 7) * 4;
            cpa16(&As[buf][r][c], &g_XH[(size_t)(m0 + r) * (DM_/2) + k0w + c]);
        }
        #pragma unroll
        for (int t = 0; t < 4; t++) {
            int idx = tid + t * 256, r = idx >> 3, c = (idx & 7) * 4;
            cpa16(&Bsn[buf][r][c], &g_WoH[(size_t)(n0 + r) * (DM_/2) + k0w + c]);
        }
        cpa_commit();
    };

    issue(0, 0);
    const int NCH = DM_ / 64;
    for (int it = 0; it < NCH; it++) {
        const int buf = it & 1;
        cpa_wait0();
        __syncthreads();
        if (it + 1 < NCH) issue((it + 1) * 32, buf ^ 1);

        #pragma unroll
        for (int ks = 0; ks < 4; ks++) {
            uint32_t af[2][4];
            #pragma unroll
            for (int mt = 0; mt < 2; mt++) {
                int rr = wm * 32 + mt * 16 + g;
                uint2 ua = *(const uint2*)&As[buf][rr][ks*8 + 2*tig];
                uint2 ub = *(const uint2*)&As[buf][rr + 8][ks*8 + 2*tig];
                af[mt][0] = ua.x; af[mt][1] = ub.x; af[mt][2] = ua.y; af[mt][3] = ub.y;
            }
            #pragma unroll
            for (int nt = 0; nt < 8; nt++) {
                int n = wn * 64 + nt * 8 + g;
                uint2 vb = *(const uint2*)&Bsn[buf][n][ks*8 + 2*tig];
                uint32_t bf[2] = {vb.x, vb.y};
                mma16(acc[0][nt], af[0], bf);
                mma16(acc[1][nt], af[1], bf);
            }
        }
    }

    #pragma unroll
    for (int mt = 0; mt < 2; mt++) {
        #pragma unroll
        for (int hf = 0; hf < 2; hf++) {
            int m = m0 + wm * 32 + mt * 16 + g + hf * 8;
            #pragma unroll
            for (int nt = 0; nt < 8; nt++) {
                int nn = n0 + wn * 64 + nt * 8 + 2 * tig;
                float2 val = hf ? make_float2(acc[mt][nt][2], acc[mt][nt][3])
                                : make_float2(acc[mt][nt][0], acc[mt][nt][1]);
                *(float2*)&y[(size_t)m * DM_ + nn] = val;
            }
        }
    }
}

// ---------------------------------------------------------------------------
extern "C" void kernel_launch(void* const* d_in, const int* in_sizes, int n_in,
                              void* d_out, int out_size)
{
    const float* q  = (const float*)d_in[0];
    const float* k  = (const float*)d_in[1];
    const float* v  = (const float*)d_in[2];
    const float* Wq = (const float*)d_in[3];
    const float* Wk = (const float*)d_in[4];
    const float* Wv = (const float*)d_in[5];
    const float* Wo = (const float*)d_in[6];
    float* y = (float*)d_out;

    const int gemm_smem = (2*128*KW + 2*128*KW) * (int)sizeof(uint32_t);       // 81920
    const int attn_smem = (4*64*KW + 2*128*KW) * (int)sizeof(uint32_t);        // 81920
    cudaFuncSetAttribute(qkv_proj_mma, cudaFuncAttributeMaxDynamicSharedMemorySize, gemm_smem);
    cudaFuncSetAttribute(attn_mma, cudaFuncAttributeMaxDynamicSharedMemorySize, attn_smem);
    cudaFuncSetAttribute(out_proj_mma, cudaFuncAttributeMaxDynamicSharedMemorySize, gemm_smem);

    cvt_pack<<<dim3(NX_ / 4096, 4), 256>>>(q, k, v, Wo);
    cvt_wT<<<dim3(DM_ / 32, H_, 3), 256>>>(Wq, Wk, Wv);
    qkv_proj_mma<<<dim3(S_ * B_ / 128, H_ / 2, 3), 256, gemm_smem>>>();
    attn_mma<<<dim3(4, B_ * H_), 256, attn_smem>>>();
    out_proj_mma<<<dim3(S_ * B_ / 128, DM_ / 128), 256, gemm_smem>>>(y);
}

// round 16
// speedup vs baseline: 1.0313x; 1.0313x over previous
#include <cuda_runtime.h>
#include <cuda_fp16.h>
#include <math.h>
#include <stdint.h>

static constexpr int B_ = 4, S_ = 1024, DM_ = 1024, H_ = 16, DK_ = 64, DV_ = 64;
static constexpr int NX_ = B_*S_*DM_;     // 4M elements (q/k/v)
static constexpr int NWO_ = DM_*H_*DV_;   // 1M elements (Wo)
static constexpr float LOG2E = 1.44269504088896f;
static constexpr int KW = 40;             // smem row stride (words); LDS.64 conflict-free

// Scratch (device globals). fp16x2 words, PERMUTED within each 8-word group:
// positions [w0,w4,w1,w5,w2,w6,w3,w7] so mma fragment pairs (w,w+4) are adjacent.
__device__ uint32_t g_qH[NX_/2], g_kH[NX_/2], g_vH[NX_/2];     // [m][512w]
__device__ uint32_t g_WqH[H_*DK_*DM_/2], g_WkH[H_*DK_*DM_/2], g_WvH[H_*DK_*DM_/2]; // [h][dk][512w]
__device__ uint32_t g_WoH[NWO_/2];                             // [d][512w]
__device__ uint32_t g_QH[B_*H_*S_*DK_/2];  // [b,h,s,32w] fp16, scaled log2e/8
__device__ uint32_t g_KH[B_*H_*S_*DK_/2];  // [b,h,s,32w]
__device__ uint32_t g_VH[B_*H_*DV_*S_/2];  // V^T: [b,h,dv][512w] pairs along seq
__device__ uint32_t g_XH[B_*S_*H_*DV_/2];  // [b,s,512w]

__device__ __forceinline__ uint32_t f2h2(float a, float b) {
    __half2 h = __floats2half2_rn(a, b);
    return *(uint32_t*)&h;
}
__device__ __forceinline__ float ex2(float x) {
    float r; asm("ex2.approx.f32 %0, %1;" : "=f"(r) : "f"(x)); return r;
}
__device__ __forceinline__ int permw(int w) {          // in-group permutation
    int t = w & 7;
    return (w & ~7) | ((t < 4) ? 2 * t : 2 * (t - 4) + 1);
}

// fp16 m16n8k16, fp32 accumulate
__device__ __forceinline__ void mma16(float* c, const uint32_t* a, const uint32_t* b) {
    asm volatile(
        "mma.sync.aligned.m16n8k16.row.col.f32.f16.f16.f32 "
        "{%0,%1,%2,%3}, {%4,%5,%6,%7}, {%8,%9}, {%0,%1,%2,%3};"
        : "+f"(c[0]), "+f"(c[1]), "+f"(c[2]), "+f"(c[3])
        : "r"(a[0]), "r"(a[1]), "r"(a[2]), "r"(a[3]), "r"(b[0]), "r"(b[1]));
}

__device__ __forceinline__ void cpa16(void* smem_ptr, const void* gptr) {
    uint32_t s = (uint32_t)__cvta_generic_to_shared(smem_ptr);
    asm volatile("cp.async.cg.shared.global [%0], [%1], 16;" :: "r"(s), "l"(gptr));
}
__device__ __forceinline__ void cpa_commit() { asm volatile("cp.async.commit_group;"); }
__device__ __forceinline__ void cpa_wait0()  { asm volatile("cp.async.wait_group 0;"); }
__device__ __forceinline__ void cpa_wait1()  { asm volatile("cp.async.wait_group 1;"); }

// ---------------------------------------------------------------------------
// Kernel 0a: convert+pack q/k/v/Wo -> permuted fp16x2 (16 elems / thread).
// ---------------------------------------------------------------------------
__global__ __launch_bounds__(256) void cvt_pack(
    const float* __restrict__ q, const float* __restrict__ k, const float* __restrict__ v,
    const float* __restrict__ Wo)
{
    const float* src; uint32_t* dst; int n;
    switch (blockIdx.y) {
        case 0: src = q;  dst = g_qH;  n = NX_;  break;
        case 1: src = k;  dst = g_kH;  n = NX_;  break;
        case 2: src = v;  dst = g_vH;  n = NX_;  break;
        default: src = Wo; dst = g_WoH; n = NWO_; break;
    }
    int i = (blockIdx.x * 256 + threadIdx.x) * 16;
    if (i < n) {
        float4 a = *(const float4*)&src[i];
        float4 b = *(const float4*)&src[i + 4];
        float4 c = *(const float4*)&src[i + 8];
        float4 d = *(const float4*)&src[i + 12];
        uint32_t w0 = f2h2(a.x, a.y), w1 = f2h2(a.z, a.w);
        uint32_t w2 = f2h2(b.x, b.y), w3 = f2h2(b.z, b.w);
        uint32_t w4 = f2h2(c.x, c.y), w5 = f2h2(c.z, c.w);
        uint32_t w6 = f2h2(d.x, d.y), w7 = f2h2(d.z, d.w);
        *(uint4*)&dst[i / 2]     = make_uint4(w0, w4, w1, w5);
        *(uint4*)&dst[i / 2 + 4] = make_uint4(w2, w6, w3, w7);
    }
}

// ---------------------------------------------------------------------------
// Kernel 0b: transpose+pack Wq/Wk/Wv -> [h][dk][dm/2 words], permuted.
// ---------------------------------------------------------------------------
__global__ __launch_bounds__(256) void cvt_wT(
    const float* __restrict__ Wq, const float* __restrict__ Wk, const float* __restrict__ Wv)
{
    const float* src; uint32_t* dst;
    if (blockIdx.z == 0)      { src = Wq; dst = g_WqH; }
    else if (blockIdx.z == 1) { src = Wk; dst = g_WkH; }
    else                      { src = Wv; dst = g_WvH; }

    const int h = blockIdx.y, d0 = blockIdx.x * 32;
    __shared__ float t[2][32][33];
    const float* Wh = src + (size_t)h * DM_ * DK_;
    for (int u = threadIdx.x; u < 2048; u += 256) {
        int i = u >> 6, nk = u & 63;
        t[nk >> 5][i][nk & 31] = Wh[(size_t)(d0 + i) * DK_ + nk];
    }
    __syncthreads();
    uint32_t* Dh = dst + (size_t)h * DK_ * (DM_ / 2);
    for (int u = threadIdx.x; u < 1024; u += 256) {
        int nk = u >> 4, i = u & 15;
        Dh[(size_t)nk * (DM_ / 2) + d0 / 2 + permw(i)] =
            f2h2(t[nk >> 5][2 * i][nk & 31], t[nk >> 5][2 * i + 1][nk & 31]);
    }
}

// ---------------------------------------------------------------------------
// Kernel 1: fused QKV projections. Block 128M x 128N(=2 heads), 8 warps
// (4m x 2n), warp 32x64, K-chunk 64 (32w), 2-stage cp.async, LDS.64 frags.
// ---------------------------------------------------------------------------
__global__ __launch_bounds__(256, 2) void qkv_proj_mma()
{
    extern __shared__ uint32_t smq[];
    uint32_t (*As)[128][KW] = (uint32_t(*)[128][KW])smq;                // 2 bufs
    uint32_t (*Bs)[128][KW] = (uint32_t(*)[128][KW])(smq + 2*128*KW);   // 2 bufs [n][kw]

    const uint32_t* x; const uint32_t* W; const int zsel = blockIdx.z;
    if (zsel == 0)      { x = g_qH; W = g_WqH; }
    else if (zsel == 1) { x = g_kH; W = g_WkH; }
    else                { x = g_vH; W = g_WvH; }

    const int m0 = blockIdx.x * 128;
    const int hp = blockIdx.y;

    const int tid = threadIdx.x, lane = tid & 31, warp = tid >> 5;
    const int wm = warp & 3, wn = warp >> 2;
    const int g = lane >> 2, tig = lane & 3;

    float acc[2][8][4];
    #pragma unroll
    for (int mt = 0; mt < 2; mt++)
        #pragma unroll
        for (int nt = 0; nt < 8; nt++)
            #pragma unroll
            for (int i = 0; i < 4; i++) acc[mt][nt][i] = 0.f;

    auto issue = [&](int k0w, int buf) {
        #pragma unroll
        for (int t = 0; t < 4; t++) {
            int idx = tid + t * 256, r = idx >> 3, c = (idx & 7) * 4;
            cpa16(&As[buf][r][c], &x[(size_t)(m0 + r) * (DM_/2) + k0w + c]);
        }
        #pragma unroll
        for (int t = 0; t < 4; t++) {
            int idx = tid + t * 256, r = idx >> 3, c = (idx & 7) * 4;
            int h = 2 * hp + (r >> 6), nk = r & 63;
            cpa16(&Bs[buf][r][c], &W[((size_t)h * DK_ + nk) * (DM_/2) + k0w + c]);
        }
        cpa_commit();
    };

    issue(0, 0);
    const int NCH = DM_ / 64;
    for (int it = 0; it < NCH; it++) {
        const int buf = it & 1;
        cpa_wait0();
        __syncthreads();
        if (it + 1 < NCH) issue((it + 1) * 32, buf ^ 1);

        #pragma unroll
        for (int ks = 0; ks < 4; ks++) {
            uint32_t af[2][4];
            #pragma unroll
            for (int mt = 0; mt < 2; mt++) {
                int rr = wm * 32 + mt * 16 + g;
                uint2 ua = *(const uint2*)&As[buf][rr][ks*8 + 2*tig];
                uint2 ub = *(const uint2*)&As[buf][rr + 8][ks*8 + 2*tig];
                af[mt][0] = ua.x; af[mt][1] = ub.x; af[mt][2] = ua.y; af[mt][3] = ub.y;
            }
            #pragma unroll
            for (int nt = 0; nt < 8; nt++) {
                int n = wn * 64 + nt * 8 + g;
                uint2 vb = *(const uint2*)&Bs[buf][n][ks*8 + 2*tig];
                uint32_t bf[2] = {vb.x, vb.y};
                mma16(acc[0][nt], af[0], bf);
                mma16(acc[1][nt], af[1], bf);
            }
        }
    }

    if (zsel == 2) {
        // ---- V: smem transpose, emit V^T [b,h,dv][s words] (permuted) ----
        __syncthreads();
        __half (*smemN)[136] = (__half(*)[136])smq;
        #pragma unroll
        for (int mt = 0; mt < 2; mt++)
            #pragma unroll
            for (int hf = 0; hf < 2; hf++) {
                int lm = wm * 32 + mt * 16 + g + hf * 8;
                #pragma unroll
                for (int nt = 0; nt < 8; nt++) {
                    int c0 = wn * 64 + nt * 8 + 2 * tig;
                    float v0 = hf ? acc[mt][nt][2] : acc[mt][nt][0];
                    float v1 = hf ? acc[mt][nt][3] : acc[mt][nt][1];
                    *(__half2*)&smemN[lm][c0] = __floats2half2_rn(v0, v1);
                }
            }
        __syncthreads();
        const int b = m0 >> 10, s0 = m0 & 1023;
        #pragma unroll
        for (int t = 0; t < 32; t++) {
            int u = tid + t * 256;
            int r = u >> 6, w = u & 63;
            int h = 2 * hp + (r >> 6), dv = r & 63;
            __half2 hh;
            hh.x = smemN[2 * w][r];
            hh.y = smemN[2 * w + 1][r];
            g_VH[(((size_t)b * H_ + h) * DV_ + dv) * (S_/2) + s0 / 2 + permw(w)] = *(uint32_t*)&hh;
        }
    } else {
        const int h = 2 * hp + wn;
        const float sc = (zsel == 0) ? 0.125f * LOG2E : 1.f;
        uint32_t* outb = (zsel == 0) ? g_QH : g_KH;
        #pragma unroll
        for (int mt = 0; mt < 2; mt++) {
            #pragma unroll
            for (int hf = 0; hf < 2; hf++) {
                int m = m0 + wm * 32 + mt * 16 + g + hf * 8;
                int b = m >> 10, s = m & 1023;
                uint32_t* op = outb + (((size_t)b * H_ + h) * S_ + s) * (DK_/2);
                #pragma unroll
                for (int nt = 0; nt < 8; nt++) {
                    float v0 = hf ? acc[mt][nt][2] : acc[mt][nt][0];
                    float v1 = hf ? acc[mt][nt][3] : acc[mt][nt][1];
                    op[(nt >> 1) * 8 + 2 * tig + (nt & 1)] = f2h2(v0 * sc, v1 * sc);
                }
            }
        }
    }
}

// ---------------------------------------------------------------------------
// Kernel 2: causal flash attention, fp16 mma16, maxless log2-softmax.
// P NEVER touches smem: S C-fragments are repacked (f2h2) directly into
// P A-fragments (identical register layout). 8 warps x 16 query rows,
// Q hoisted to registers. Grid (4,64); qt = 7-bx then bx (18 tiles/block).
// ---------------------------------------------------------------------------
__global__ __launch_bounds__(256, 2) void attn_mma()
{
    extern __shared__ uint32_t sm[];
    uint32_t (*Ks)[64][KW] = (uint32_t(*)[64][KW])sm;                // 2 bufs [key][kw]
    uint32_t (*Vs)[64][KW] = (uint32_t(*)[64][KW])(sm + 2*64*KW);    // 2 bufs [dv][keyw]
    uint32_t (*Qst)[KW]    = (uint32_t(*)[KW])(sm + 4*64*KW);        // 128 x KW (Q staging)

    const int bh = blockIdx.y;
    const int b = bh >> 4, h = bh & 15;
    const int tid = threadIdx.x, lane = tid & 31, warp = tid >> 5;
    const int g = lane >> 2, tig = lane & 3;

    const uint32_t* Kg = g_KH + (size_t)bh * S_ * (DK_/2);
    const uint32_t* Vg = g_VH + (size_t)bh * DV_ * (S_/2);

    for (int ph = 0; ph < 2; ph++) {
        const int qt = ph == 0 ? 7 - (int)blockIdx.x : (int)blockIdx.x;
        const uint32_t* Qg = g_QH + (size_t)bh * S_ * (DK_/2) + (size_t)qt * 128 * (DK_/2);

        __syncthreads();     // all warps done with prior phase smem
        #pragma unroll
        for (int t = 0; t < 4; t++) {
            int idx = tid + t * 256, r = idx >> 3, c = (idx & 7) * 4;
            cpa16(&Qst[r][c], &Qg[r * (DK_/2) + c]);
        }
        cpa_commit(); cpa_wait0();
        __syncthreads();

        uint32_t qf[4][4];
        {
            int rr = warp * 16 + g;
            #pragma unroll
            for (int ks = 0; ks < 4; ks++) {
                uint2 ua = *(const uint2*)&Qst[rr][ks*8 + 2*tig];
                uint2 ub = *(const uint2*)&Qst[rr + 8][ks*8 + 2*tig];
                qf[ks][0] = ua.x; qf[ks][1] = ub.x; qf[ks][2] = ua.y; qf[ks][3] = ub.y;
            }
        }

        auto issueKV = [&](int j, int buf) {
            const uint32_t* Kt = Kg + (size_t)j * 64 * (DK_/2);
            #pragma unroll
            for (int t = 0; t < 2; t++) {
                int idx = tid + t * 256, r = idx >> 3, c = (idx & 7) * 4;
                cpa16(&Ks[buf][r][c], &Kt[r * (DK_/2) + c]);
            }
            #pragma unroll
            for (int t = 0; t < 2; t++) {
                int idx = tid + t * 256, r = idx >> 3, c = (idx & 7) * 4;
                cpa16(&Vs[buf][r][c], &Vg[r * (S_/2) + j * 32 + c]);
            }
            cpa_commit();
        };

        float O[8][4];
        #pragma unroll
        for (int nt = 0; nt < 8; nt++)
            #pragma unroll
            for (int i = 0; i < 4; i++) O[nt][i] = 0.f;
        float lst[2] = {0.f, 0.f};

        const int base = qt * 128 + warp * 16;
        const int jmax = 2 * qt + 1;

        issueKV(0, 0);

        for (int j = 0; j <= jmax; j++) {
            const int buf = j & 1;
            __syncthreads();             // prior tile's compute done
            if (j < jmax) { issueKV(j + 1, buf ^ 1); cpa_wait1(); }
            else          { cpa_wait0(); }
            __syncthreads();             // tile j visible

            if (j * 64 > base + 15) continue;

            // ---- S = Q K^T (log2 domain) ----
            float Sf[8][4];
            #pragma unroll
            for (int nt = 0; nt < 8; nt++)
                #pragma unroll
                for (int i = 0; i < 4; i++) Sf[nt][i] = 0.f;

            #pragma unroll
            for (int ks = 0; ks < 4; ks++) {
                #pragma unroll
                for (int nt = 0; nt < 8; nt++) {
                    uint2 vb = *(const uint2*)&Ks[buf][nt*8 + g][ks*8 + 2*tig];
                    uint32_t bf[2] = {vb.x, vb.y};
                    mma16(Sf[nt], qf[ks], bf);
                }
            }

            // ---- causal mask ----
            if ((j + 1) * 64 > base) {
                int r0 = base + g - j * 64, r1 = r0 + 8;
                #pragma unroll
                for (int nt = 0; nt < 8; nt++) {
                    int c0 = nt * 8 + 2 * tig, c1 = c0 + 1;
                    if (c0 > r0) Sf[nt][0] = -1e30f;
                    if (c1 > r0) Sf[nt][1] = -1e30f;
                    if (c0 > r1) Sf[nt][2] = -1e30f;
                    if (c1 > r1) Sf[nt][3] = -1e30f;
                }
            }

            // ---- maxless softmax: p = 2^s, packed DIRECTLY to A-fragments ----
            uint32_t pA[4][4];
            float ls0 = 0.f, ls1 = 0.f;
            #pragma unroll
            for (int kt = 0; kt < 4; kt++) {
                const int nt0 = 2 * kt, nt1 = nt0 + 1;
                float a0 = ex2(Sf[nt0][0]), a1 = ex2(Sf[nt0][1]);
                float a2 = ex2(Sf[nt0][2]), a3 = ex2(Sf[nt0][3]);
                float b0 = ex2(Sf[nt1][0]), b1 = ex2(Sf[nt1][1]);
                float b2 = ex2(Sf[nt1][2]), b3 = ex2(Sf[nt1][3]);
                ls0 += (a0 + a1) + (b0 + b1);
                ls1 += (a2 + a3) + (b2 + b3);
                pA[kt][0] = f2h2(a0, a1);   // row g,   k-low
                pA[kt][1] = f2h2(a2, a3);   // row g+8, k-low
                pA[kt][2] = f2h2(b0, b1);   // row g,   k-high
                pA[kt][3] = f2h2(b2, b3);   // row g+8, k-high
            }
            lst[0] += ls0; lst[1] += ls1;

            // ---- O += P V ----
            #pragma unroll
            for (int kt = 0; kt < 4; kt++) {
                #pragma unroll
                for (int nt = 0; nt < 8; nt++) {
                    uint2 vb = *(const uint2*)&Vs[buf][nt*8 + g][kt*8 + 2*tig];
                    uint32_t bf[2] = {vb.x, vb.y};
                    mma16(O[nt], pA[kt], bf);
                }
            }
        }

        // finish row sums (each row spans 4 lanes) and write X
        #pragma unroll
        for (int hp = 0; hp < 2; hp++) {
            float ls = hp ? lst[1] : lst[0];
            ls += __shfl_xor_sync(0xffffffffu, ls, 1);
            ls += __shfl_xor_sync(0xffffffffu, ls, 2);
            const float rl = 1.f / ls;
            const int row = base + g + 8 * hp;
            uint32_t* xp = g_XH + ((size_t)b * S_ + row) * (H_ * DV_ / 2) + h * (DV_/2);
            #pragma unroll
            for (int nt = 0; nt < 8; nt++)
                xp[(nt >> 1) * 8 + 2 * tig + (nt & 1)] =
                    f2h2(O[nt][2*hp] * rl, O[nt][2*hp + 1] * rl);
        }
    }
}

// ---------------------------------------------------------------------------
// Kernel 3: output projection. Block 128x128, 8 warps (4m x 2n), warp 32x64,
// K-chunk 64, 2-stage ring, LDS.64 fragments.
// ---------------------------------------------------------------------------
__global__ __launch_bounds__(256, 2) void out_proj_mma(float* __restrict__ y)
{
    extern __shared__ uint32_t smo[];
    uint32_t (*As)[128][KW]  = (uint32_t(*)[128][KW])smo;
    uint32_t (*Bsn)[128][KW] = (uint32_t(*)[128][KW])(smo + 2*128*KW);

    const int m0 = blockIdx.x * 128;
    const int n0 = blockIdx.y * 128;

    const int tid = threadIdx.x, lane = tid & 31, warp = tid >> 5;
    const int wm = warp & 3, wn = warp >> 2;
    const int g = lane >> 2, tig = lane & 3;

    float acc[2][8][4];
    #pragma unroll
    for (int mt = 0; mt < 2; mt++)
        #pragma unroll
        for (int nt = 0; nt < 8; nt++)
            #pragma unroll
            for (int i = 0; i < 4; i++) acc[mt][nt][i] = 0.f;

    auto issue = [&](int k0w, int buf) {
        #pragma unroll
        for (int t = 0; t < 4; t++) {
            int idx = tid + t * 256, r = idx >> 3, c = (idx & 7) * 4;
            cpa16(&As[buf][r][c], &g_XH[(size_t)(m0 + r) * (DM_/2) + k0w + c]);
        }
        #pragma unroll
        for (int t = 0; t < 4; t++) {
            int idx = tid + t * 256, r = idx >> 3, c = (idx & 7) * 4;
            cpa16(&Bsn[buf][r][c], &g_WoH[(size_t)(n0 + r) * (DM_/2) + k0w + c]);
        }
        cpa_commit();
    };

    issue(0, 0);
    const int NCH = DM_ / 64;
    for (int it = 0; it < NCH; it++) {
        const int buf = it & 1;
        cpa_wait0();
        __syncthreads();
        if (it + 1 < NCH) issue((it + 1) * 32, buf ^ 1);

        #pragma unroll
        for (int ks = 0; ks < 4; ks++) {
            uint32_t af[2][4];
            #pragma unroll
            for (int mt = 0; mt < 2; mt++) {
                int rr = wm * 32 + mt * 16 + g;
                uint2 ua = *(const uint2*)&As[buf][rr][ks*8 + 2*tig];
                uint2 ub = *(const uint2*)&As[buf][rr + 8][ks*8 + 2*tig];
                af[mt][0] = ua.x; af[mt][1] = ub.x; af[mt][2] = ua.y; af[mt][3] = ub.y;
            }
            #pragma unroll
            for (int nt = 0; nt < 8; nt++) {
                int n = wn * 64 + nt * 8 + g;
                uint2 vb = *(const uint2*)&Bsn[buf][n][ks*8 + 2*tig];
                uint32_t bf[2] = {vb.x, vb.y};
                mma16(acc[0][nt], af[0], bf);
                mma16(acc[1][nt], af[1], bf);
            }
        }
    }

    #pragma unroll
    for (int mt = 0; mt < 2; mt++) {
        #pragma unroll
        for (int hf = 0; hf < 2; hf++) {
            int m = m0 + wm * 32 + mt * 16 + g + hf * 8;
            #pragma unroll
            for (int nt = 0; nt < 8; nt++) {
                int nn = n0 + wn * 64 + nt * 8 + 2 * tig;
                float2 val = hf ? make_float2(acc[mt][nt][2], acc[mt][nt][3])
                                : make_float2(acc[mt][nt][0], acc[mt][nt][1]);
                *(float2*)&y[(size_t)m * DM_ + nn] = val;
            }
        }
    }
}

// ---------------------------------------------------------------------------
extern "C" void kernel_launch(void* const* d_in, const int* in_sizes, int n_in,
                              void* d_out, int out_size)
{
    const float* q  = (const float*)d_in[0];
    const float* k  = (const float*)d_in[1];
    const float* v  = (const float*)d_in[2];
    const float* Wq = (const float*)d_in[3];
    const float* Wk = (const float*)d_in[4];
    const float* Wv = (const float*)d_in[5];
    const float* Wo = (const float*)d_in[6];
    float* y = (float*)d_out;

    const int gemm_smem = (2*128*KW + 2*128*KW) * (int)sizeof(uint32_t);       // 81920
    const int attn_smem = (4*64*KW + 128*KW) * (int)sizeof(uint32_t);          // 61440
    cudaFuncSetAttribute(qkv_proj_mma, cudaFuncAttributeMaxDynamicSharedMemorySize, gemm_smem);
    cudaFuncSetAttribute(attn_mma, cudaFuncAttributeMaxDynamicSharedMemorySize, attn_smem);
    cudaFuncSetAttribute(out_proj_mma, cudaFuncAttributeMaxDynamicSharedMemorySize, gemm_smem);

    cvt_pack<<<dim3(NX_ / 4096, 4), 256>>>(q, k, v, Wo);
    cvt_wT<<<dim3(DM_ / 32, H_, 3), 256>>>(Wq, Wk, Wv);
    qkv_proj_mma<<<dim3(S_ * B_ / 128, H_ / 2, 3), 256, gemm_smem>>>();
    attn_mma<<<dim3(4, B_ * H_), 256, attn_smem>>>();
    out_proj_mma<<<dim3(S_ * B_ / 128, DM_ / 128), 256, gemm_smem>>>(y);
}